// round 3
// baseline (speedup 1.0000x reference)
#include <cuda_runtime.h>
#include <math.h>

#define BDIM 2
#define TDIM 2048
#define CDIM 1024
#define HDIM 64
#define NH   16
#define NKV  8
#define MROWS (BDIM*TDIM)   // 4096

// ---------------- scratch (device globals: no allocation allowed) -------------
__device__ float g_q_raw[(size_t)MROWS * CDIM];        // 16 MB
__device__ float g_k_raw[(size_t)MROWS * NKV * HDIM];  // 8 MB
__device__ float g_v_raw[(size_t)MROWS * NKV * HDIM];  // 8 MB
__device__ float g_sq[(size_t)BDIM * NH * TDIM];
__device__ float g_sk[(size_t)BDIM * NKV * TDIM];
__device__ float g_y[(size_t)MROWS * CDIM];            // 16 MB

// ---------------- SGEMM: C[M,N] = A[M,K] @ B[N,K]^T (all row-major) ----------
// BM=BN=128, BK=8, 256 threads, 8x8 per-thread microtile, register prefetch.
__global__ __launch_bounds__(256) void sgemm_nt(
    const float* __restrict__ A, const float* __restrict__ B,
    float* __restrict__ C, int M, int N, int K)
{
    __shared__ float As[8][128];
    __shared__ float Bs[8][128];

    const int tid  = threadIdx.x;
    const int m0   = blockIdx.y * 128;
    const int n0   = blockIdx.x * 128;
    const int lrow = tid >> 1;           // 0..127
    const int lk4  = (tid & 1) * 4;      // 0 or 4

    const float* Aptr = A + (size_t)(m0 + lrow) * K + lk4;
    const float* Bptr = B + (size_t)(n0 + lrow) * K + lk4;

    const int ty = tid >> 4;             // 0..15
    const int tx = tid & 15;             // 0..15

    float acc[8][8];
    #pragma unroll
    for (int i = 0; i < 8; i++)
        #pragma unroll
        for (int j = 0; j < 8; j++) acc[i][j] = 0.f;

    float4 a4 = *(const float4*)Aptr;
    float4 b4 = *(const float4*)Bptr;

    for (int kt = 0; kt < K; kt += 8) {
        As[lk4+0][lrow] = a4.x; As[lk4+1][lrow] = a4.y;
        As[lk4+2][lrow] = a4.z; As[lk4+3][lrow] = a4.w;
        Bs[lk4+0][lrow] = b4.x; Bs[lk4+1][lrow] = b4.y;
        Bs[lk4+2][lrow] = b4.z; Bs[lk4+3][lrow] = b4.w;
        __syncthreads();

        if (kt + 8 < K) {   // prefetch next K-tile while computing this one
            a4 = *(const float4*)(Aptr + kt + 8);
            b4 = *(const float4*)(Bptr + kt + 8);
        }

        #pragma unroll
        for (int kk = 0; kk < 8; kk++) {
            float a[8], b[8];
            #pragma unroll
            for (int i = 0; i < 8; i++) a[i] = As[kk][ty*8 + i];
            #pragma unroll
            for (int j = 0; j < 8; j++) b[j] = Bs[kk][tx*8 + j];
            #pragma unroll
            for (int i = 0; i < 8; i++)
                #pragma unroll
                for (int j = 0; j < 8; j++)
                    acc[i][j] = fmaf(a[i], b[j], acc[i][j]);
        }
        __syncthreads();
    }

    #pragma unroll
    for (int i = 0; i < 8; i++) {
        float* crow = C + (size_t)(m0 + ty*8 + i) * N + n0 + tx*8;
        float4 c0 = make_float4(acc[i][0], acc[i][1], acc[i][2], acc[i][3]);
        float4 c1 = make_float4(acc[i][4], acc[i][5], acc[i][6], acc[i][7]);
        ((float4*)crow)[0] = c0;
        ((float4*)crow)[1] = c1;
    }
}

// ------------- RoPE + RMSnorm + braid dot: one warp per (b,t,h) row ----------
// raw layout: [(b*T+t) * (nheads*64) + h*64 + d]. Output: s[(b*nheads+h)*T + t].
__global__ __launch_bounds__(256) void rope_braid(
    const float* __restrict__ raw, float* __restrict__ sout,
    const float* __restrict__ cosb, const float* __restrict__ sinb,
    const float* __restrict__ wb, int nheads)
{
    const int rid  = blockIdx.x * 8 + (threadIdx.x >> 5);
    const int lane = threadIdx.x & 31;
    const int total = BDIM * TDIM * nheads;
    if (rid >= total) return;

    const int h  = rid % nheads;
    const int bt = rid / nheads;
    const int t  = bt % TDIM;
    const int b  = bt / TDIM;

    const float* base = raw + (size_t)bt * (nheads * HDIM) + h * HDIM;
    const float x1 = base[lane];
    const float x2 = base[lane + 32];
    const float c  = cosb[t*32 + lane];
    const float s  = sinb[t*32 + lane];

    const float r1 = x1*c + x2*s;
    const float r2 = x2*c - x1*s;

    float ss = r1*r1 + r2*r2;
    #pragma unroll
    for (int o = 16; o; o >>= 1) ss += __shfl_xor_sync(0xffffffffu, ss, o);
    const float scale = rsqrtf(ss * (1.0f/64.0f) + 1e-6f);

    float sv = (r1*wb[lane] + r2*wb[lane+32]) * scale;
    #pragma unroll
    for (int o = 16; o; o >>= 1) sv += __shfl_xor_sync(0xffffffffu, sv, o);

    if (lane == 0)
        sout[((size_t)b*nheads + h) * TDIM + t] = sv;
}

// ---------------- attention: y[t,:] = (1/sqrt(T)) sum_{s<=t} sig(sq+sk) v[s,:]
// grid: (T/128 [reversed for heavy-first], B*NH), 128 threads, 1 thread = 1 t.
__global__ __launch_bounds__(128) void braid_attn()
{
    const int bh = blockIdx.y;           // b*NH + h
    const int b  = bh >> 4;
    const int h  = bh & 15;
    const int kh = h >> 1;
    const int t0 = (int)(gridDim.x - 1 - blockIdx.x) * 128;
    const int tl = threadIdx.x;
    const int t  = t0 + tl;

    const float sq = g_sq[(size_t)bh * TDIM + t];
    const float* vbase  = g_v_raw + (size_t)b * TDIM * (NKV*HDIM) + kh * HDIM;
    const float* skbase = g_sk + ((size_t)b * NKV + kh) * TDIM;

    __shared__ float vs[128][64];
    __shared__ float sks[128];

    float acc[64];
    #pragma unroll
    for (int i = 0; i < 64; i++) acc[i] = 0.f;

    for (int s0 = 0; s0 <= t0; s0 += 128) {
        // cooperative coalesced load of v tile (128 s-rows x 64 d) into smem
        #pragma unroll
        for (int i = 0; i < 16; i++) {
            int j  = i * 128 + tl;        // 0..2047 float4-chunks
            int sr = j >> 4;              // s row 0..127
            int d4 = j & 15;              // float4 within row
            float4 v4 = ((const float4*)(vbase + (size_t)(s0 + sr) * (NKV*HDIM)))[d4];
            ((float4*)vs[sr])[d4] = v4;
        }
        sks[tl] = skbase[s0 + tl];
        __syncthreads();

        if (s0 < t0) {                    // fully unmasked tile
            #pragma unroll 2
            for (int s = 0; s < 128; s++) {
                float p = __fdividef(1.0f, 1.0f + __expf(-(sq + sks[s])));
                const float4* vv = (const float4*)vs[s];
                #pragma unroll
                for (int i = 0; i < 16; i++) {
                    float4 v4 = vv[i];
                    acc[i*4+0] = fmaf(p, v4.x, acc[i*4+0]);
                    acc[i*4+1] = fmaf(p, v4.y, acc[i*4+1]);
                    acc[i*4+2] = fmaf(p, v4.z, acc[i*4+2]);
                    acc[i*4+3] = fmaf(p, v4.w, acc[i*4+3]);
                }
            }
        } else {                          // diagonal tile: causal mask
            for (int s = 0; s < 128; s++) {
                float p = (s0 + s <= t)
                          ? __fdividef(1.0f, 1.0f + __expf(-(sq + sks[s])))
                          : 0.0f;
                const float4* vv = (const float4*)vs[s];
                #pragma unroll
                for (int i = 0; i < 16; i++) {
                    float4 v4 = vv[i];
                    acc[i*4+0] = fmaf(p, v4.x, acc[i*4+0]);
                    acc[i*4+1] = fmaf(p, v4.y, acc[i*4+1]);
                    acc[i*4+2] = fmaf(p, v4.z, acc[i*4+2]);
                    acc[i*4+3] = fmaf(p, v4.w, acc[i*4+3]);
                }
            }
        }
        __syncthreads();
    }

    const float inv = 1.0f / (45.25483399593904f + 1e-6f);  // sqrt(2048)+1e-6
    float* yrow = g_y + (size_t)(b*TDIM + t) * CDIM + h * HDIM;
    #pragma unroll
    for (int i = 0; i < 16; i++) {
        float4 o = make_float4(acc[i*4+0]*inv, acc[i*4+1]*inv,
                               acc[i*4+2]*inv, acc[i*4+3]*inv);
        ((float4*)yrow)[i] = o;
    }
}

// -----------------------------------------------------------------------------
extern "C" void kernel_launch(void* const* d_in, const int* in_sizes, int n_in,
                              void* d_out, int out_size)
{
    const float* x     = (const float*)d_in[0];
    const float* cosb  = (const float*)d_in[1];
    const float* sinb  = (const float*)d_in[2];
    const float* Wq    = (const float*)d_in[3];
    const float* Wk    = (const float*)d_in[4];
    const float* Wv    = (const float*)d_in[5];
    const float* Wproj = (const float*)d_in[6];
    const float* wb    = (const float*)d_in[7];
    float* out = (float*)d_out;

    float *q_raw, *k_raw, *v_raw, *sq, *sk, *y;
    cudaGetSymbolAddress((void**)&q_raw, g_q_raw);
    cudaGetSymbolAddress((void**)&k_raw, g_k_raw);
    cudaGetSymbolAddress((void**)&v_raw, g_v_raw);
    cudaGetSymbolAddress((void**)&sq,    g_sq);
    cudaGetSymbolAddress((void**)&sk,    g_sk);
    cudaGetSymbolAddress((void**)&y,     g_y);

    // QKV projections
    sgemm_nt<<<dim3(CDIM/128,        MROWS/128), 256>>>(x, Wq, q_raw, MROWS, CDIM,      CDIM);
    sgemm_nt<<<dim3((NKV*HDIM)/128,  MROWS/128), 256>>>(x, Wk, k_raw, MROWS, NKV*HDIM, CDIM);
    sgemm_nt<<<dim3((NKV*HDIM)/128,  MROWS/128), 256>>>(x, Wv, v_raw, MROWS, NKV*HDIM, CDIM);

    // RoPE + RMSnorm + braid scalar (q and k collapse to s_q / s_k)
    rope_braid<<<(BDIM*TDIM*NH  + 7) / 8, 256>>>(q_raw, sq, cosb, sinb, wb, NH);
    rope_braid<<<(BDIM*TDIM*NKV + 7) / 8, 256>>>(k_raw, sk, cosb, sinb, wb, NKV);

    // sigmoid-braid causal attention -> y (already scaled, laid out [B,T,C])
    braid_attn<<<dim3(TDIM/128, BDIM*NH), 128>>>();

    // output projection
    sgemm_nt<<<dim3(CDIM/128, MROWS/128), 256>>>(y, Wproj, out, MROWS, CDIM, CDIM);
}

// round 8
// speedup vs baseline: 1.3525x; 1.3525x over previous
#include <cuda_runtime.h>
#include <cuda_bf16.h>
#include <math.h>
#include <stdint.h>

#define BDIM 2
#define TDIM 2048
#define CDIM 1024
#define HDIM 64
#define NH   16
#define NKV  8
#define MROWS (BDIM*TDIM)   // 4096

// Arch-specific feature gate: tcgen05 only exists in the sm_103a pass.
#if defined(__CUDA_ARCH__) && defined(__CUDA_ARCH_FEAT_SM103_ALL)
#define HAS_TCGEN05 1
#else
#define HAS_TCGEN05 0
#endif

// ---------------- scratch (device globals: no allocation allowed) -------------
__device__ float g_q_raw[(size_t)MROWS * CDIM];
__device__ float g_k_raw[(size_t)MROWS * NKV * HDIM];
__device__ float g_v_raw[(size_t)MROWS * NKV * HDIM];
__device__ float g_sq[(size_t)BDIM * NH * TDIM];
__device__ float g_sk[(size_t)BDIM * NKV * TDIM];

__device__ __nv_bfloat16 g_xhi[(size_t)MROWS * CDIM];
__device__ __nv_bfloat16 g_xlo[(size_t)MROWS * CDIM];
__device__ __nv_bfloat16 g_wqh[(size_t)CDIM * CDIM];
__device__ __nv_bfloat16 g_wql[(size_t)CDIM * CDIM];
__device__ __nv_bfloat16 g_wkh[(size_t)(NKV*HDIM) * CDIM];
__device__ __nv_bfloat16 g_wkl[(size_t)(NKV*HDIM) * CDIM];
__device__ __nv_bfloat16 g_wvh[(size_t)(NKV*HDIM) * CDIM];
__device__ __nv_bfloat16 g_wvl[(size_t)(NKV*HDIM) * CDIM];
__device__ __nv_bfloat16 g_wph[(size_t)CDIM * CDIM];
__device__ __nv_bfloat16 g_wpl[(size_t)CDIM * CDIM];
__device__ __nv_bfloat16 g_yhi[(size_t)MROWS * CDIM];
__device__ __nv_bfloat16 g_ylo[(size_t)MROWS * CDIM];

// =================== tcgen05 helpers (guarded) ===============================
#if HAS_TCGEN05
__device__ __forceinline__ uint32_t smem_u32(const void* p) {
    uint32_t a;
    asm("{ .reg .u64 t; cvta.to.shared.u64 t, %1; cvt.u32.u64 %0, t; }" : "=r"(a) : "l"(p));
    return a;
}
__device__ __forceinline__ uint32_t elect_one() {
    uint32_t pred;
    asm volatile("{\n\t.reg .pred p;\n\telect.sync _|p, 0xFFFFFFFF;\n\tselp.b32 %0, 1, 0, p;\n\t}" : "=r"(pred));
    return pred;
}
#define TC_ALLOC(smem_addr, n)  asm volatile("tcgen05.alloc.cta_group::1.sync.aligned.shared::cta.b32 [%0], %1;" :: "r"(smem_addr), "r"(n) : "memory")
#define TC_DEALLOC(tmem, n)     asm volatile("tcgen05.dealloc.cta_group::1.sync.aligned.b32 %0, %1;" :: "r"(tmem), "r"(n))
#define TC_COMMIT(mbar)         asm volatile("tcgen05.commit.cta_group::1.mbarrier::arrive::one.shared::cluster.b64 [%0];" :: "r"(mbar) : "memory")
#define TC_FENCE_AFTER()        asm volatile("tcgen05.fence::after_thread_sync;" ::: "memory")
#define TC_FENCE_BEFORE()       asm volatile("tcgen05.fence::before_thread_sync;" ::: "memory")
#define TC_WAIT_LD()            asm volatile("tcgen05.wait::ld.sync.aligned;" ::: "memory")
#define MBAR_INIT(mbar, cnt)    asm volatile("mbarrier.init.shared.b64 [%0], %1;" :: "r"(mbar), "r"(cnt) : "memory")

__device__ __forceinline__ void mbar_wait(uint32_t mbar, uint32_t parity) {
    asm volatile(
        "{\n\t.reg .pred P;\n\t"
        "W%=:\n\t"
        "mbarrier.try_wait.parity.acquire.cta.shared::cta.b64 P, [%0], %1, 0x989680;\n\t"
        "@P bra.uni D%=;\n\t"
        "bra.uni W%=;\n\t"
        "D%=:\n\t}"
        :: "r"(mbar), "r"(parity) : "memory");
}
__device__ __forceinline__ void tc_mma_f16_ss(uint32_t d_tmem, uint64_t a_desc, uint64_t b_desc,
                                              uint32_t idesc, uint32_t en) {
    asm volatile(
        "{\n\t.reg .pred p;\n\tsetp.ne.u32 p, %4, 0;\n\t"
        "tcgen05.mma.cta_group::1.kind::f16 [%0], %1, %2, %3, {%5, %5, %5, %5}, p;\n\t}"
        :: "r"(d_tmem), "l"(a_desc), "l"(b_desc), "r"(idesc), "r"(en), "r"(0u) : "memory");
}
__device__ __forceinline__ void ldtm_x32(uint32_t* r, uint32_t tmem) {
    asm volatile(
        "tcgen05.ld.sync.aligned.32x32b.x32.b32 "
        "{%0, %1, %2, %3, %4, %5, %6, %7, %8, %9, %10, %11, %12, %13, %14, %15, "
        " %16, %17, %18, %19, %20, %21, %22, %23, %24, %25, %26, %27, %28, %29, %30, %31}, [%32];"
        : "=r"(r[0]), "=r"(r[1]), "=r"(r[2]), "=r"(r[3]), "=r"(r[4]), "=r"(r[5]), "=r"(r[6]), "=r"(r[7]),
          "=r"(r[8]), "=r"(r[9]), "=r"(r[10]), "=r"(r[11]), "=r"(r[12]), "=r"(r[13]), "=r"(r[14]), "=r"(r[15]),
          "=r"(r[16]), "=r"(r[17]), "=r"(r[18]), "=r"(r[19]), "=r"(r[20]), "=r"(r[21]), "=r"(r[22]), "=r"(r[23]),
          "=r"(r[24]), "=r"(r[25]), "=r"(r[26]), "=r"(r[27]), "=r"(r[28]), "=r"(r[29]), "=r"(r[30]), "=r"(r[31])
        : "r"(tmem));
}
#define DESC_BASE ((uint64_t(2) << 61) | (uint64_t(1) << 46) | (uint64_t(64) << 32) | (uint64_t(1) << 16))
__device__ __forceinline__ uint64_t mk_desc(uint32_t addr) {
    return DESC_BASE | ((uint64_t)(addr >> 4) & 0x3FFF);
}
#endif // HAS_TCGEN05

// ================= bf16-split GEMM: C[M,N] = sum_k A[m,k]*B[n,k] =============
// tcgen05 path: 3-pass K extension (Ahi,Bhi)+(Ahi,Blo)+(Alo,Bhi), tile 128x128,
// KT=64, double-buffered SMEM. Fallback path: FFMA tiled GEMM on (hi+lo).
#define SOFF_TM  0
#define SOFF_MB  8
#define SOFF_A0  1024
#define SOFF_B0  (1024 + 16384)
#define SOFF_A1  (1024 + 32768)
#define SOFF_B1  (1024 + 49152)
#define SMEM_GEMM (1024 + 65536)

// idesc: F32 acc, BF16 x BF16, N=128, M=128 (bit-matches 0x8080490 recipe)
#define GEMM_IDESC ((1u<<4) | (1u<<7) | (1u<<10) | ((128u/8)<<17) | ((128u/16)<<24))

__global__ __launch_bounds__(256)
#if HAS_TCGEN05
__cluster_dims__(1, 1, 1)
#endif
void gemm3_bf16(
    const __nv_bfloat16* __restrict__ Ahi, const __nv_bfloat16* __restrict__ Alo,
    const __nv_bfloat16* __restrict__ Bhi, const __nv_bfloat16* __restrict__ Blo,
    float* __restrict__ C, int M, int N, int K)
{
#if HAS_TCGEN05
    extern __shared__ char smem[];
    const uint32_t sbase = smem_u32(smem);
    const int tid  = threadIdx.x;
    const int wid  = tid >> 5;
    const int lane = tid & 31;
    const int m0 = blockIdx.y * 128;
    const int n0 = blockIdx.x * 128;

    if (wid == 0) { TC_ALLOC(sbase + SOFF_TM, 128); }   // no relinquish: avoids
    if (tid == 0) {                                     // relinquish-before-alloc race
        MBAR_INIT(sbase + SOFF_MB, 1);
        MBAR_INIT(sbase + SOFF_MB + 8, 1);
    }
    __syncthreads();
    uint32_t tmem;
    asm volatile("ld.shared.b32 %0, [%1];" : "=r"(tmem) : "r"(sbase + SOFF_TM));

    const uint32_t abuf[2] = { sbase + SOFF_A0, sbase + SOFF_A1 };
    const uint32_t bbuf[2] = { sbase + SOFF_B0, sbase + SOFF_B1 };
    char* const abufp[2] = { smem + SOFF_A0, smem + SOFF_A1 };
    char* const bbufp[2] = { smem + SOFF_B0, smem + SOFF_B1 };

    const int ipp = K / 64;          // iters per pass
    const int NIT = 3 * ipp;

    // fill buffer `nb` for iteration `it`: A tile 128x64 bf16 (16KB) + B (16KB)
    auto load_iter = [&](int it, int nb) {
        const int pass = it / ipp;
        const int kk   = (it - pass * ipp) * 64;
        const __nv_bfloat16* Asrc = (pass < 2) ? Ahi : Alo;
        const __nv_bfloat16* Bsrc = (pass == 1) ? Blo : Bhi;
        #pragma unroll
        for (int i = 0; i < 8; i++) {
            const int j = i * 256 + tid;          // 0..2047 16B-chunks
            const bool isA = j < 1024;
            const int jj  = isA ? j : j - 1024;
            const int row = jj >> 3;              // 0..127
            const int c16 = jj & 7;               // 16B chunk within 128B row
            const __nv_bfloat16* src = isA
                ? Asrc + ((size_t)(m0 + row) * K + kk + c16 * 8)
                : Bsrc + ((size_t)(n0 + row) * K + kk + c16 * 8);
            uint4 v = *(const uint4*)src;
            uint32_t off = row * 128 + c16 * 16;
            uint32_t sw  = off ^ ((off >> 3) & 0x70);
            *(uint4*)((isA ? abufp[nb] : bbufp[nb]) + sw) = v;
        }
        TC_FENCE_BEFORE();           // generic->async proxy (example-proven pair)
    };

    load_iter(0, 0);
    __syncthreads();

    uint32_t ph[2] = {0u, 0u};
    for (int it = 0; it < NIT; ++it) {
        const int buf = it & 1;
        if (wid == 0) {
            TC_FENCE_AFTER();        // completes the fence pair across syncthreads
            if (elect_one()) {
                uint64_t ad = mk_desc(abuf[buf]);
                uint64_t bd = mk_desc(bbuf[buf]);
                #pragma unroll
                for (int ks = 0; ks < 4; ks++)
                    tc_mma_f16_ss(tmem, ad + ks * 2, bd + ks * 2, GEMM_IDESC,
                                  (it == 0 && ks == 0) ? 0u : 1u);
                TC_COMMIT(sbase + SOFF_MB + 8 * buf);
            }
        }
        if (it + 1 < NIT) {
            const int nb = buf ^ 1;
            if (it > 0) { mbar_wait(sbase + SOFF_MB + 8 * nb, ph[nb]); ph[nb] ^= 1; }
            load_iter(it + 1, nb);
        }
        __syncthreads();
    }

    const int lb = (NIT - 1) & 1;
    mbar_wait(sbase + SOFF_MB + 8 * lb, ph[lb]);
    TC_FENCE_AFTER();

    if (wid < 4) {
        uint32_t r[64];
        #pragma unroll
        for (int half = 0; half < 2; half++) {
            ldtm_x32(r,      tmem + half * 64);
            ldtm_x32(r + 32, tmem + half * 64 + 32);
            TC_WAIT_LD();
            float* crow = C + (size_t)(m0 + wid * 32 + lane) * N + n0 + half * 64;
            #pragma unroll
            for (int c = 0; c < 64; c += 4) {
                float4 o = make_float4(__uint_as_float(r[c]),   __uint_as_float(r[c+1]),
                                       __uint_as_float(r[c+2]), __uint_as_float(r[c+3]));
                *(float4*)(crow + c) = o;
            }
        }
        TC_FENCE_BEFORE();
    }
    __syncthreads();
    if (wid == 0) { TC_DEALLOC(tmem, 128); }
#else
    // -------- FFMA fallback (non-103a compilation pass; functionally exact) --
    extern __shared__ char smem_raw[];
    float* As = (float*)smem_raw;          // [8][128]
    float* Bs = As + 8 * 128;              // [8][128]

    const int tid  = threadIdx.x;
    const int m0   = blockIdx.y * 128;
    const int n0   = blockIdx.x * 128;
    const int lrow = tid >> 1;
    const int lk4  = (tid & 1) * 4;
    const int ty   = tid >> 4;
    const int tx   = tid & 15;

    const __nv_bfloat16* Ah = Ahi + (size_t)(m0 + lrow) * K;
    const __nv_bfloat16* Al = Alo + (size_t)(m0 + lrow) * K;
    const __nv_bfloat16* Bh = Bhi + (size_t)(n0 + lrow) * K;
    const __nv_bfloat16* Bl = Blo + (size_t)(n0 + lrow) * K;

    float acc[8][8];
    #pragma unroll
    for (int i = 0; i < 8; i++)
        #pragma unroll
        for (int j = 0; j < 8; j++) acc[i][j] = 0.f;

    for (int kt = 0; kt < K; kt += 8) {
        #pragma unroll
        for (int j = 0; j < 4; j++) {
            As[(lk4+j)*128 + lrow] = __bfloat162float(Ah[kt+lk4+j]) + __bfloat162float(Al[kt+lk4+j]);
            Bs[(lk4+j)*128 + lrow] = __bfloat162float(Bh[kt+lk4+j]) + __bfloat162float(Bl[kt+lk4+j]);
        }
        __syncthreads();
        #pragma unroll
        for (int kk = 0; kk < 8; kk++) {
            float a[8], b[8];
            #pragma unroll
            for (int i = 0; i < 8; i++) a[i] = As[kk*128 + ty*8 + i];
            #pragma unroll
            for (int j = 0; j < 8; j++) b[j] = Bs[kk*128 + tx*8 + j];
            #pragma unroll
            for (int i = 0; i < 8; i++)
                #pragma unroll
                for (int j = 0; j < 8; j++)
                    acc[i][j] = fmaf(a[i], b[j], acc[i][j]);
        }
        __syncthreads();
    }
    #pragma unroll
    for (int i = 0; i < 8; i++) {
        float* crow = C + (size_t)(m0 + ty*8 + i) * N + n0 + tx*8;
        ((float4*)crow)[0] = make_float4(acc[i][0], acc[i][1], acc[i][2], acc[i][3]);
        ((float4*)crow)[1] = make_float4(acc[i][4], acc[i][5], acc[i][6], acc[i][7]);
    }
#endif
}

// ---------------- fp32 -> bf16 hi/lo split (elementwise) ---------------------
__global__ __launch_bounds__(256) void split_bf16(
    const float* __restrict__ src, __nv_bfloat16* __restrict__ hi,
    __nv_bfloat16* __restrict__ lo, int n4)
{
    int i = blockIdx.x * 256 + threadIdx.x;
    if (i >= n4) return;
    float4 v = ((const float4*)src)[i];
    float f[4] = {v.x, v.y, v.z, v.w};
    __nv_bfloat16 h[4], l[4];
    #pragma unroll
    for (int j = 0; j < 4; j++) {
        h[j] = __float2bfloat16(f[j]);
        l[j] = __float2bfloat16(f[j] - __bfloat162float(h[j]));
    }
    ((__nv_bfloat162*)hi)[2*i]   = __halves2bfloat162(h[0], h[1]);
    ((__nv_bfloat162*)hi)[2*i+1] = __halves2bfloat162(h[2], h[3]);
    ((__nv_bfloat162*)lo)[2*i]   = __halves2bfloat162(l[0], l[1]);
    ((__nv_bfloat162*)lo)[2*i+1] = __halves2bfloat162(l[2], l[3]);
}

// ------------- RoPE + RMSnorm + braid dot: one warp per (b,t,h) row ----------
__global__ __launch_bounds__(256) void rope_braid(
    const float* __restrict__ raw, float* __restrict__ sout,
    const float* __restrict__ cosb, const float* __restrict__ sinb,
    const float* __restrict__ wb, int nheads)
{
    const int rid  = blockIdx.x * 8 + (threadIdx.x >> 5);
    const int lane = threadIdx.x & 31;
    const int total = BDIM * TDIM * nheads;
    if (rid >= total) return;

    const int h  = rid % nheads;
    const int bt = rid / nheads;
    const int t  = bt % TDIM;
    const int b  = bt / TDIM;

    const float* base = raw + (size_t)bt * (nheads * HDIM) + h * HDIM;
    const float x1 = base[lane];
    const float x2 = base[lane + 32];
    const float c  = cosb[t*32 + lane];
    const float s  = sinb[t*32 + lane];

    const float r1 = x1*c + x2*s;
    const float r2 = x2*c - x1*s;

    float ss = r1*r1 + r2*r2;
    #pragma unroll
    for (int o = 16; o; o >>= 1) ss += __shfl_xor_sync(0xffffffffu, ss, o);
    const float scale = rsqrtf(ss * (1.0f/64.0f) + 1e-6f);

    float sv = (r1*wb[lane] + r2*wb[lane+32]) * scale;
    #pragma unroll
    for (int o = 16; o; o >>= 1) sv += __shfl_xor_sync(0xffffffffu, sv, o);

    if (lane == 0)
        sout[((size_t)b*nheads + h) * TDIM + t] = sv;
}

// ---------------- attention: y[t,:] = (1/sqrt(T)) sum_{s<=t} sig(sq+sk) v[s,:]
__global__ __launch_bounds__(128) void braid_attn()
{
    const int bh = blockIdx.y;           // b*NH + h
    const int b  = bh >> 4;
    const int h  = bh & 15;
    const int kh = h >> 1;
    const int t0 = (int)(gridDim.x - 1 - blockIdx.x) * 128;
    const int tl = threadIdx.x;
    const int t  = t0 + tl;

    const float sq = g_sq[(size_t)bh * TDIM + t];
    const float* vbase  = g_v_raw + (size_t)b * TDIM * (NKV*HDIM) + kh * HDIM;
    const float* skbase = g_sk + ((size_t)b * NKV + kh) * TDIM;

    __shared__ float vs[128][64];
    __shared__ float sks[128];

    float acc[64];
    #pragma unroll
    for (int i = 0; i < 64; i++) acc[i] = 0.f;

    for (int s0 = 0; s0 <= t0; s0 += 128) {
        #pragma unroll
        for (int i = 0; i < 16; i++) {
            int j  = i * 128 + tl;
            int sr = j >> 4;
            int d4 = j & 15;
            float4 v4 = ((const float4*)(vbase + (size_t)(s0 + sr) * (NKV*HDIM)))[d4];
            ((float4*)vs[sr])[d4] = v4;
        }
        sks[tl] = skbase[s0 + tl];
        __syncthreads();

        if (s0 < t0) {
            #pragma unroll 2
            for (int s = 0; s < 128; s++) {
                float p = __fdividef(1.0f, 1.0f + __expf(-(sq + sks[s])));
                const float4* vv = (const float4*)vs[s];
                #pragma unroll
                for (int i = 0; i < 16; i++) {
                    float4 v4 = vv[i];
                    acc[i*4+0] = fmaf(p, v4.x, acc[i*4+0]);
                    acc[i*4+1] = fmaf(p, v4.y, acc[i*4+1]);
                    acc[i*4+2] = fmaf(p, v4.z, acc[i*4+2]);
                    acc[i*4+3] = fmaf(p, v4.w, acc[i*4+3]);
                }
            }
        } else {
            for (int s = 0; s < 128; s++) {
                float p = (s0 + s <= t)
                          ? __fdividef(1.0f, 1.0f + __expf(-(sq + sks[s])))
                          : 0.0f;
                const float4* vv = (const float4*)vs[s];
                #pragma unroll
                for (int i = 0; i < 16; i++) {
                    float4 v4 = vv[i];
                    acc[i*4+0] = fmaf(p, v4.x, acc[i*4+0]);
                    acc[i*4+1] = fmaf(p, v4.y, acc[i*4+1]);
                    acc[i*4+2] = fmaf(p, v4.z, acc[i*4+2]);
                    acc[i*4+3] = fmaf(p, v4.w, acc[i*4+3]);
                }
            }
        }
        __syncthreads();
    }

    // write y as bf16 hi/lo (feeds the proj GEMM directly, no split pass)
    const float inv = 1.0f / (45.25483399593904f + 1e-6f);  // sqrt(2048)+1e-6
    __nv_bfloat16* yh = g_yhi + (size_t)(b*TDIM + t) * CDIM + h * HDIM;
    __nv_bfloat16* yl = g_ylo + (size_t)(b*TDIM + t) * CDIM + h * HDIM;
    #pragma unroll
    for (int i = 0; i < 64; i += 2) {
        float v0 = acc[i] * inv, v1 = acc[i+1] * inv;
        __nv_bfloat16 h0 = __float2bfloat16(v0), h1 = __float2bfloat16(v1);
        __nv_bfloat16 l0 = __float2bfloat16(v0 - __bfloat162float(h0));
        __nv_bfloat16 l1 = __float2bfloat16(v1 - __bfloat162float(h1));
        *(__nv_bfloat162*)(yh + i) = __halves2bfloat162(h0, h1);
        *(__nv_bfloat162*)(yl + i) = __halves2bfloat162(l0, l1);
    }
}

// -----------------------------------------------------------------------------
extern "C" void kernel_launch(void* const* d_in, const int* in_sizes, int n_in,
                              void* d_out, int out_size)
{
    const float* x     = (const float*)d_in[0];
    const float* cosb  = (const float*)d_in[1];
    const float* sinb  = (const float*)d_in[2];
    const float* Wq    = (const float*)d_in[3];
    const float* Wk    = (const float*)d_in[4];
    const float* Wv    = (const float*)d_in[5];
    const float* Wproj = (const float*)d_in[6];
    const float* wb    = (const float*)d_in[7];
    float* out = (float*)d_out;

    float *q_raw, *k_raw, *v_raw, *sq, *sk;
    cudaGetSymbolAddress((void**)&q_raw, g_q_raw);
    cudaGetSymbolAddress((void**)&k_raw, g_k_raw);
    cudaGetSymbolAddress((void**)&v_raw, g_v_raw);
    cudaGetSymbolAddress((void**)&sq,    g_sq);
    cudaGetSymbolAddress((void**)&sk,    g_sk);

    __nv_bfloat16 *xhi, *xlo, *wqh, *wql, *wkh, *wkl, *wvh, *wvl, *wph, *wpl, *yhi, *ylo;
    cudaGetSymbolAddress((void**)&xhi, g_xhi);  cudaGetSymbolAddress((void**)&xlo, g_xlo);
    cudaGetSymbolAddress((void**)&wqh, g_wqh);  cudaGetSymbolAddress((void**)&wql, g_wql);
    cudaGetSymbolAddress((void**)&wkh, g_wkh);  cudaGetSymbolAddress((void**)&wkl, g_wkl);
    cudaGetSymbolAddress((void**)&wvh, g_wvh);  cudaGetSymbolAddress((void**)&wvl, g_wvl);
    cudaGetSymbolAddress((void**)&wph, g_wph);  cudaGetSymbolAddress((void**)&wpl, g_wpl);
    cudaGetSymbolAddress((void**)&yhi, g_yhi);  cudaGetSymbolAddress((void**)&ylo, g_ylo);

    cudaFuncSetAttribute(gemm3_bf16, cudaFuncAttributeMaxDynamicSharedMemorySize, SMEM_GEMM);

    // hi/lo bf16 splits of x and weights
    {
        int n4;
        n4 = MROWS*CDIM/4;          split_bf16<<<(n4+255)/256, 256>>>(x,     xhi, xlo, n4);
        n4 = CDIM*CDIM/4;           split_bf16<<<(n4+255)/256, 256>>>(Wq,    wqh, wql, n4);
        n4 = (NKV*HDIM)*CDIM/4;     split_bf16<<<(n4+255)/256, 256>>>(Wk,    wkh, wkl, n4);
        n4 = (NKV*HDIM)*CDIM/4;     split_bf16<<<(n4+255)/256, 256>>>(Wv,    wvh, wvl, n4);
        n4 = CDIM*CDIM/4;           split_bf16<<<(n4+255)/256, 256>>>(Wproj, wph, wpl, n4);
    }

    // QKV projections on tcgen05 (bf16 split x3 for fp32 accuracy)
    gemm3_bf16<<<dim3(CDIM/128,       MROWS/128), 256, SMEM_GEMM>>>(xhi, xlo, wqh, wql, q_raw, MROWS, CDIM,     CDIM);
    gemm3_bf16<<<dim3((NKV*HDIM)/128, MROWS/128), 256, SMEM_GEMM>>>(xhi, xlo, wkh, wkl, k_raw, MROWS, NKV*HDIM, CDIM);
    gemm3_bf16<<<dim3((NKV*HDIM)/128, MROWS/128), 256, SMEM_GEMM>>>(xhi, xlo, wvh, wvl, v_raw, MROWS, NKV*HDIM, CDIM);

    // RoPE + RMSnorm + braid scalar
    rope_braid<<<(BDIM*TDIM*NH  + 7) / 8, 256>>>(q_raw, sq, cosb, sinb, wb, NH);
    rope_braid<<<(BDIM*TDIM*NKV + 7) / 8, 256>>>(k_raw, sk, cosb, sinb, wb, NKV);

    // sigmoid-braid causal attention -> y (bf16 hi/lo)
    braid_attn<<<dim3(TDIM/128, BDIM*NH), 128>>>();

    // output projection
    gemm3_bf16<<<dim3(CDIM/128, MROWS/128), 256, SMEM_GEMM>>>(yhi, ylo, wph, wpl, out, MROWS, CDIM, CDIM);
}

// round 13
// speedup vs baseline: 1.9702x; 1.4567x over previous
#include <cuda_runtime.h>
#include <cuda_bf16.h>
#include <math.h>
#include <stdint.h>

#define BDIM 2
#define TDIM 2048
#define CDIM 1024
#define HDIM 64
#define NH   16
#define NKV  8
#define MROWS (BDIM*TDIM)   // 4096
#define QKV_COLS 2048       // 1024 q | 512 k | 512 v

// Arch-specific feature gate: tcgen05 only exists in the sm_103a pass.
#if defined(__CUDA_ARCH__) && defined(__CUDA_ARCH_FEAT_SM103_ALL)
#define HAS_TCGEN05 1
#else
#define HAS_TCGEN05 0
#endif

// ---------------- scratch (device globals: no allocation allowed) -------------
__device__ float g_qkv[(size_t)MROWS * QKV_COLS];     // fused q|k|v raw, 32MB
__device__ float g_sq[(size_t)BDIM * NH * TDIM];
__device__ float g_sk[(size_t)BDIM * NKV * TDIM];

__device__ __nv_bfloat16 g_xhi[(size_t)MROWS * CDIM];
__device__ __nv_bfloat16 g_xlo[(size_t)MROWS * CDIM];
__device__ __nv_bfloat16 g_wqkvh[(size_t)QKV_COLS * CDIM];   // Wq|Wk|Wv hi
__device__ __nv_bfloat16 g_wqkvl[(size_t)QKV_COLS * CDIM];   // Wq|Wk|Wv lo
__device__ __nv_bfloat16 g_wph[(size_t)CDIM * CDIM];
__device__ __nv_bfloat16 g_wpl[(size_t)CDIM * CDIM];
__device__ __nv_bfloat16 g_yhi[(size_t)MROWS * CDIM];
__device__ __nv_bfloat16 g_ylo[(size_t)MROWS * CDIM];

// =================== tcgen05 helpers (guarded) ===============================
#if HAS_TCGEN05
__device__ __forceinline__ uint32_t smem_u32(const void* p) {
    uint32_t a;
    asm("{ .reg .u64 t; cvta.to.shared.u64 t, %1; cvt.u32.u64 %0, t; }" : "=r"(a) : "l"(p));
    return a;
}
__device__ __forceinline__ uint32_t elect_one() {
    uint32_t pred;
    asm volatile("{\n\t.reg .pred p;\n\telect.sync _|p, 0xFFFFFFFF;\n\tselp.b32 %0, 1, 0, p;\n\t}" : "=r"(pred));
    return pred;
}
#define TC_ALLOC(smem_addr, n)  asm volatile("tcgen05.alloc.cta_group::1.sync.aligned.shared::cta.b32 [%0], %1;" :: "r"(smem_addr), "r"(n) : "memory")
#define TC_DEALLOC(tmem, n)     asm volatile("tcgen05.dealloc.cta_group::1.sync.aligned.b32 %0, %1;" :: "r"(tmem), "r"(n))
#define TC_COMMIT(mbar)         asm volatile("tcgen05.commit.cta_group::1.mbarrier::arrive::one.shared::cluster.b64 [%0];" :: "r"(mbar) : "memory")
#define TC_FENCE_AFTER()        asm volatile("tcgen05.fence::after_thread_sync;" ::: "memory")
#define TC_FENCE_BEFORE()       asm volatile("tcgen05.fence::before_thread_sync;" ::: "memory")
#define TC_WAIT_LD()            asm volatile("tcgen05.wait::ld.sync.aligned;" ::: "memory")
#define MBAR_INIT(mbar, cnt)    asm volatile("mbarrier.init.shared.b64 [%0], %1;" :: "r"(mbar), "r"(cnt) : "memory")

__device__ __forceinline__ void mbar_wait(uint32_t mbar, uint32_t parity) {
    asm volatile(
        "{\n\t.reg .pred P;\n\t"
        "W%=:\n\t"
        "mbarrier.try_wait.parity.acquire.cta.shared::cta.b64 P, [%0], %1, 0x989680;\n\t"
        "@P bra.uni D%=;\n\t"
        "bra.uni W%=;\n\t"
        "D%=:\n\t}"
        :: "r"(mbar), "r"(parity) : "memory");
}
__device__ __forceinline__ void tc_mma_f16_ss(uint32_t d_tmem, uint64_t a_desc, uint64_t b_desc,
                                              uint32_t idesc, uint32_t en) {
    asm volatile(
        "{\n\t.reg .pred p;\n\tsetp.ne.u32 p, %4, 0;\n\t"
        "tcgen05.mma.cta_group::1.kind::f16 [%0], %1, %2, %3, {%5, %5, %5, %5}, p;\n\t}"
        :: "r"(d_tmem), "l"(a_desc), "l"(b_desc), "r"(idesc), "r"(en), "r"(0u) : "memory");
}
__device__ __forceinline__ void ldtm_x32(uint32_t* r, uint32_t tmem) {
    asm volatile(
        "tcgen05.ld.sync.aligned.32x32b.x32.b32 "
        "{%0, %1, %2, %3, %4, %5, %6, %7, %8, %9, %10, %11, %12, %13, %14, %15, "
        " %16, %17, %18, %19, %20, %21, %22, %23, %24, %25, %26, %27, %28, %29, %30, %31}, [%32];"
        : "=r"(r[0]), "=r"(r[1]), "=r"(r[2]), "=r"(r[3]), "=r"(r[4]), "=r"(r[5]), "=r"(r[6]), "=r"(r[7]),
          "=r"(r[8]), "=r"(r[9]), "=r"(r[10]), "=r"(r[11]), "=r"(r[12]), "=r"(r[13]), "=r"(r[14]), "=r"(r[15]),
          "=r"(r[16]), "=r"(r[17]), "=r"(r[18]), "=r"(r[19]), "=r"(r[20]), "=r"(r[21]), "=r"(r[22]), "=r"(r[23]),
          "=r"(r[24]), "=r"(r[25]), "=r"(r[26]), "=r"(r[27]), "=r"(r[28]), "=r"(r[29]), "=r"(r[30]), "=r"(r[31])
        : "r"(tmem));
}
#define DESC_BASE ((uint64_t(2) << 61) | (uint64_t(1) << 46) | (uint64_t(64) << 32) | (uint64_t(1) << 16))
__device__ __forceinline__ uint64_t mk_desc(uint32_t addr) {
    return DESC_BASE | ((uint64_t)(addr >> 4) & 0x3FFF);
}
#endif // HAS_TCGEN05

// ================= bf16-split GEMM: C[M,N] = sum_k A[m,k]*B[n,k] =============
#define SOFF_TM  0
#define SOFF_MB  8
#define SOFF_A0  1024
#define SOFF_B0  (1024 + 16384)
#define SOFF_A1  (1024 + 32768)
#define SOFF_B1  (1024 + 49152)
#define SMEM_GEMM (1024 + 65536)

// idesc: F32 acc, BF16 x BF16, N=128, M=128
#define GEMM_IDESC ((1u<<4) | (1u<<7) | (1u<<10) | ((128u/8)<<17) | ((128u/16)<<24))

__global__ __launch_bounds__(256)
#if HAS_TCGEN05
__cluster_dims__(1, 1, 1)
#endif
void gemm3_bf16(
    const __nv_bfloat16* __restrict__ Ahi, const __nv_bfloat16* __restrict__ Alo,
    const __nv_bfloat16* __restrict__ Bhi, const __nv_bfloat16* __restrict__ Blo,
    float* __restrict__ C, int M, int NC, int K)
{
#if HAS_TCGEN05
    extern __shared__ char smem[];
    const uint32_t sbase = smem_u32(smem);
    const int tid  = threadIdx.x;
    const int wid  = tid >> 5;
    const int lane = tid & 31;
    const int m0 = blockIdx.y * 128;
    const int n0 = blockIdx.x * 128;

    if (wid == 0) { TC_ALLOC(sbase + SOFF_TM, 128); }
    if (tid == 0) {
        MBAR_INIT(sbase + SOFF_MB, 1);
        MBAR_INIT(sbase + SOFF_MB + 8, 1);
    }
    __syncthreads();
    uint32_t tmem;
    asm volatile("ld.shared.b32 %0, [%1];" : "=r"(tmem) : "r"(sbase + SOFF_TM));

    const uint32_t abuf[2] = { sbase + SOFF_A0, sbase + SOFF_A1 };
    const uint32_t bbuf[2] = { sbase + SOFF_B0, sbase + SOFF_B1 };
    char* const abufp[2] = { smem + SOFF_A0, smem + SOFF_A1 };
    char* const bbufp[2] = { smem + SOFF_B0, smem + SOFF_B1 };

    const int ipp = K / 64;
    const int NIT = 3 * ipp;

    auto load_iter = [&](int it, int nb) {
        const int pass = it / ipp;
        const int kk   = (it - pass * ipp) * 64;
        const __nv_bfloat16* Asrc = (pass < 2) ? Ahi : Alo;
        const __nv_bfloat16* Bsrc = (pass == 1) ? Blo : Bhi;
        #pragma unroll
        for (int i = 0; i < 8; i++) {
            const int j = i * 256 + tid;
            const bool isA = j < 1024;
            const int jj  = isA ? j : j - 1024;
            const int row = jj >> 3;
            const int c16 = jj & 7;
            const __nv_bfloat16* src = isA
                ? Asrc + ((size_t)(m0 + row) * K + kk + c16 * 8)
                : Bsrc + ((size_t)(n0 + row) * K + kk + c16 * 8);
            uint4 v = *(const uint4*)src;
            uint32_t off = row * 128 + c16 * 16;
            uint32_t sw  = off ^ ((off >> 3) & 0x70);
            *(uint4*)((isA ? abufp[nb] : bbufp[nb]) + sw) = v;
        }
        TC_FENCE_BEFORE();
    };

    load_iter(0, 0);
    __syncthreads();

    uint32_t ph[2] = {0u, 0u};
    for (int it = 0; it < NIT; ++it) {
        const int buf = it & 1;
        if (wid == 0) {
            TC_FENCE_AFTER();
            if (elect_one()) {
                uint64_t ad = mk_desc(abuf[buf]);
                uint64_t bd = mk_desc(bbuf[buf]);
                #pragma unroll
                for (int ks = 0; ks < 4; ks++)
                    tc_mma_f16_ss(tmem, ad + ks * 2, bd + ks * 2, GEMM_IDESC,
                                  (it == 0 && ks == 0) ? 0u : 1u);
                TC_COMMIT(sbase + SOFF_MB + 8 * buf);
            }
        }
        if (it + 1 < NIT) {
            const int nb = buf ^ 1;
            if (it > 0) { mbar_wait(sbase + SOFF_MB + 8 * nb, ph[nb]); ph[nb] ^= 1; }
            load_iter(it + 1, nb);
        }
        __syncthreads();
    }

    const int lb = (NIT - 1) & 1;
    mbar_wait(sbase + SOFF_MB + 8 * lb, ph[lb]);
    TC_FENCE_AFTER();

    if (wid < 4) {
        uint32_t r[64];
        #pragma unroll
        for (int half = 0; half < 2; half++) {
            ldtm_x32(r,      tmem + half * 64);
            ldtm_x32(r + 32, tmem + half * 64 + 32);
            TC_WAIT_LD();
            float* crow = C + (size_t)(m0 + wid * 32 + lane) * NC + n0 + half * 64;
            #pragma unroll
            for (int c = 0; c < 64; c += 4) {
                float4 o = make_float4(__uint_as_float(r[c]),   __uint_as_float(r[c+1]),
                                       __uint_as_float(r[c+2]), __uint_as_float(r[c+3]));
                *(float4*)(crow + c) = o;
            }
        }
        TC_FENCE_BEFORE();
    }
    __syncthreads();
    if (wid == 0) { TC_DEALLOC(tmem, 128); }
#else
    // -------- FFMA fallback (non-103a pass; functionally exact) --------------
    extern __shared__ char smem_raw[];
    float* As = (float*)smem_raw;
    float* Bs = As + 8 * 128;

    const int tid  = threadIdx.x;
    const int m0   = blockIdx.y * 128;
    const int n0   = blockIdx.x * 128;
    const int lrow = tid >> 1;
    const int lk4  = (tid & 1) * 4;
    const int ty   = tid >> 4;
    const int tx   = tid & 15;

    const __nv_bfloat16* Ah = Ahi + (size_t)(m0 + lrow) * K;
    const __nv_bfloat16* Al = Alo + (size_t)(m0 + lrow) * K;
    const __nv_bfloat16* Bh = Bhi + (size_t)(n0 + lrow) * K;
    const __nv_bfloat16* Bl = Blo + (size_t)(n0 + lrow) * K;

    float acc[8][8];
    #pragma unroll
    for (int i = 0; i < 8; i++)
        #pragma unroll
        for (int j = 0; j < 8; j++) acc[i][j] = 0.f;

    for (int kt = 0; kt < K; kt += 8) {
        #pragma unroll
        for (int j = 0; j < 4; j++) {
            As[(lk4+j)*128 + lrow] = __bfloat162float(Ah[kt+lk4+j]) + __bfloat162float(Al[kt+lk4+j]);
            Bs[(lk4+j)*128 + lrow] = __bfloat162float(Bh[kt+lk4+j]) + __bfloat162float(Bl[kt+lk4+j]);
        }
        __syncthreads();
        #pragma unroll
        for (int kk = 0; kk < 8; kk++) {
            float a[8], b[8];
            #pragma unroll
            for (int i = 0; i < 8; i++) a[i] = As[kk*128 + ty*8 + i];
            #pragma unroll
            for (int j = 0; j < 8; j++) b[j] = Bs[kk*128 + tx*8 + j];
            #pragma unroll
            for (int i = 0; i < 8; i++)
                #pragma unroll
                for (int j = 0; j < 8; j++)
                    acc[i][j] = fmaf(a[i], b[j], acc[i][j]);
        }
        __syncthreads();
    }
    #pragma unroll
    for (int i = 0; i < 8; i++) {
        float* crow = C + (size_t)(m0 + ty*8 + i) * NC + n0 + tx*8;
        ((float4*)crow)[0] = make_float4(acc[i][0], acc[i][1], acc[i][2], acc[i][3]);
        ((float4*)crow)[1] = make_float4(acc[i][4], acc[i][5], acc[i][6], acc[i][7]);
    }
#endif
}

// ---------------- fp32 -> bf16 hi/lo split (elementwise) ---------------------
__global__ __launch_bounds__(256) void split_bf16(
    const float* __restrict__ src, __nv_bfloat16* __restrict__ hi,
    __nv_bfloat16* __restrict__ lo, int n4)
{
    int i = blockIdx.x * 256 + threadIdx.x;
    if (i >= n4) return;
    float4 v = ((const float4*)src)[i];
    float f[4] = {v.x, v.y, v.z, v.w};
    __nv_bfloat16 h[4], l[4];
    #pragma unroll
    for (int j = 0; j < 4; j++) {
        h[j] = __float2bfloat16(f[j]);
        l[j] = __float2bfloat16(f[j] - __bfloat162float(h[j]));
    }
    ((__nv_bfloat162*)hi)[2*i]   = __halves2bfloat162(h[0], h[1]);
    ((__nv_bfloat162*)hi)[2*i+1] = __halves2bfloat162(h[2], h[3]);
    ((__nv_bfloat162*)lo)[2*i]   = __halves2bfloat162(l[0], l[1]);
    ((__nv_bfloat162*)lo)[2*i+1] = __halves2bfloat162(l[2], l[3]);
}

// ------------- RoPE + RMSnorm + braid dot: one warp per (b,t,h) row ----------
__global__ __launch_bounds__(256) void rope_braid(
    const float* __restrict__ qkv, float* __restrict__ sout,
    const float* __restrict__ cosb, const float* __restrict__ sinb,
    const float* __restrict__ wb, int nheads, int col0)
{
    const int rid  = blockIdx.x * 8 + (threadIdx.x >> 5);
    const int lane = threadIdx.x & 31;
    const int total = BDIM * TDIM * nheads;
    if (rid >= total) return;

    const int h  = rid % nheads;
    const int bt = rid / nheads;
    const int t  = bt % TDIM;
    const int b  = bt / TDIM;

    const float* base = qkv + (size_t)bt * QKV_COLS + col0 + h * HDIM;
    const float x1 = base[lane];
    const float x2 = base[lane + 32];
    const float c  = cosb[t*32 + lane];
    const float s  = sinb[t*32 + lane];

    const float r1 = x1*c + x2*s;
    const float r2 = x2*c - x1*s;

    float ss = r1*r1 + r2*r2;
    #pragma unroll
    for (int o = 16; o; o >>= 1) ss += __shfl_xor_sync(0xffffffffu, ss, o);
    const float scale = rsqrtf(ss * (1.0f/64.0f) + 1e-6f);

    float sv = (r1*wb[lane] + r2*wb[lane+32]) * scale;
    #pragma unroll
    for (int o = 16; o; o >>= 1) sv += __shfl_xor_sync(0xffffffffu, sv, o);

    if (lane == 0)
        sout[((size_t)b*nheads + h) * TDIM + t] = sv;
}

// ========== tensor-core attention: y = (1/sqrt T) sig(sq+sk)|causal @ v ======
// per CTA: one (b,h) and one 128-row t-tile. P and V^T in SMEM as bf16 hi/lo,
// 3-term split MMA (Ph*Vh + Ph*Vl + Pl*Vh) accumulated in TMEM D[128x64] fp32.
#define ATT_TMPTR 0
#define ATT_MBAR  8
#define ATT_PH    1024                 // P hi  [128t x 128s] bf16 = 32KB
#define ATT_PL    (1024 + 32768)       // P lo
#define ATT_VH    (1024 + 65536)       // V^T hi [64d x 128s] bf16 = 16KB
#define ATT_VL    (1024 + 65536 + 16384)
#define ATT_ESK   (1024 + 65536 + 32768)   // 128 floats, AFTER tiles (no overlap!)
#define SMEM_ATTN (1024 + 65536 + 32768 + 512)   // 99840

// idesc: F32 acc, BF16 x BF16, N=64, M=128
#define ATT_IDESC ((1u<<4) | (1u<<7) | (1u<<10) | ((64u/8)<<17) | ((128u/16)<<24))

#define SW128(x) ((x) ^ (((x) >> 3) & 0x70))
// blocked-atom byte offsets (atom = 8 rows x 64 bf16, per test_mma_iter recipe)
__device__ __forceinline__ uint32_t a_off(int t, int s) {   // A: 128 rows -> 16 atom-rows
    return (uint32_t)(((t >> 3) + (s >> 6) * 16) * 1024 + (t & 7) * 128 + (s & 63) * 2);
}
__device__ __forceinline__ uint32_t b_off(int d, int s) {   // B: 64 rows -> 8 atom-rows
    return (uint32_t)(((d >> 3) + (s >> 6) * 8) * 1024 + (d & 7) * 128 + (s & 63) * 2);
}

__global__ __launch_bounds__(128)
#if HAS_TCGEN05
__cluster_dims__(1, 1, 1)
#endif
void braid_attn_tc()
{
    const int bh = blockIdx.y;
    const int b  = bh >> 4;
    const int h  = bh & 15;
    const int kh = h >> 1;
    const int t0 = (int)(gridDim.x - 1 - blockIdx.x) * 128;
    const int tl = threadIdx.x;
    const int t  = t0 + tl;
    const float sq = g_sq[(size_t)bh * TDIM + t];
    const float* skb  = g_sk + ((size_t)b * NKV + kh) * TDIM;
    const float* vsrc = g_qkv + (size_t)b * TDIM * QKV_COLS + 1536 + kh * HDIM;

#if HAS_TCGEN05
    extern __shared__ char smem[];
    const uint32_t sbase = smem_u32(smem);
    const int wid  = tl >> 5;

    if (wid == 0) { TC_ALLOC(sbase + ATT_TMPTR, 64); }
    if (tl == 0)  { MBAR_INIT(sbase + ATT_MBAR, 1); }
    __syncthreads();
    uint32_t tmem;
    asm volatile("ld.shared.b32 %0, [%1];" : "=r"(tmem) : "r"(sbase + ATT_TMPTR));

    // E = exp(-sq), clamped so E*esk can never hit 0*inf
    const float E = __expf(-fminf(fmaxf(sq, -80.f), 80.f));
    float* eskp = (float*)(smem + ATT_ESK);

    uint32_t ph = 0;
    const int ntiles = t0 / 128 + 1;
    for (int it = 0; it < ntiles; ++it) {
        const int s0 = it * 128;
        if (it > 0) { mbar_wait(sbase + ATT_MBAR, ph); ph ^= 1; }   // SMEM free

        // per-tile exp(-sk) table (shared across all t threads)
        {
            float skv = skb[s0 + tl];
            eskp[tl] = __expf(-fminf(fmaxf(skv, -80.f), 80.f));
        }

        // V^T tile: [64 d rows x 128 s] bf16 hi/lo, blocked-atom + SW128
        #pragma unroll 4
        for (int i = 0; i < 32; i++) {
            const int idx = i * 128 + tl;
            const int d  = idx & 63;
            const int s  = (idx >> 6) * 2;
            const float v0 = vsrc[(size_t)(s0 + s)     * QKV_COLS + d];
            const float v1 = vsrc[(size_t)(s0 + s + 1) * QKV_COLS + d];
            __nv_bfloat162 h2 = __floats2bfloat162_rn(v0, v1);
            float l0 = v0 - __bfloat162float(__low2bfloat16(h2));
            float l1 = v1 - __bfloat162float(__high2bfloat16(h2));
            __nv_bfloat162 l2 = __floats2bfloat162_rn(l0, l1);
            const uint32_t off = SW128(b_off(d, s));
            *(__nv_bfloat162*)(smem + ATT_VH + off) = h2;
            *(__nv_bfloat162*)(smem + ATT_VL + off) = l2;
        }
        __syncthreads();   // esk table complete before P loop

        // P row for this thread's t: p = 1/(1 + E*esk[s]), causal-masked
        const int lim = (s0 == t0) ? tl : 127;
        #pragma unroll 4
        for (int j = 0; j < 64; j++) {
            const int s = 2 * j;
            const float2 e2 = ((const float2*)eskp)[j];
            float p0 = (s     <= lim) ? __fdividef(1.f, fmaf(E, e2.x, 1.f)) : 0.f;
            float p1 = (s + 1 <= lim) ? __fdividef(1.f, fmaf(E, e2.y, 1.f)) : 0.f;
            __nv_bfloat162 h2 = __floats2bfloat162_rn(p0, p1);
            float l0 = p0 - __bfloat162float(__low2bfloat16(h2));
            float l1 = p1 - __bfloat162float(__high2bfloat16(h2));
            __nv_bfloat162 l2 = __floats2bfloat162_rn(l0, l1);
            const uint32_t off = SW128(a_off(tl, s));
            *(__nv_bfloat162*)(smem + ATT_PH + off) = h2;
            *(__nv_bfloat162*)(smem + ATT_PL + off) = l2;
        }
        TC_FENCE_BEFORE();
        __syncthreads();

        if (wid == 0) {
            TC_FENCE_AFTER();
            if (elect_one()) {
                const uint64_t pa_h = mk_desc(sbase + ATT_PH);
                const uint64_t pa_l = mk_desc(sbase + ATT_PL);
                const uint64_t vb_h = mk_desc(sbase + ATT_VH);
                const uint64_t vb_l = mk_desc(sbase + ATT_VL);
                #pragma unroll
                for (int term = 0; term < 3; term++) {
                    const uint64_t ad = (term == 2) ? pa_l : pa_h;
                    const uint64_t bd = (term == 1) ? vb_l : vb_h;
                    #pragma unroll
                    for (int ks = 0; ks < 8; ks++) {
                        const uint64_t ao = (ks < 4) ? (uint64_t)(ks * 2) : (uint64_t)(1024 + (ks - 4) * 2);
                        const uint64_t bo = (ks < 4) ? (uint64_t)(ks * 2) : (uint64_t)(512  + (ks - 4) * 2);
                        tc_mma_f16_ss(tmem, ad + ao, bd + bo, ATT_IDESC,
                                      (it == 0 && term == 0 && ks == 0) ? 0u : 1u);
                    }
                }
                TC_COMMIT(sbase + ATT_MBAR);
            }
        }
    }

    mbar_wait(sbase + ATT_MBAR, ph);
    TC_FENCE_AFTER();

    // epilogue: D[t row = tl][d 0..63] fp32 from TMEM -> y bf16 hi/lo
    uint32_t r[64];
    ldtm_x32(r,      tmem);
    ldtm_x32(r + 32, tmem + 32);
    TC_WAIT_LD();
    TC_FENCE_BEFORE();

    const float inv = 1.0f / (45.25483399593904f + 1e-6f);
    __nv_bfloat16* yh = g_yhi + (size_t)(b * TDIM + t) * CDIM + h * HDIM;
    __nv_bfloat16* yl = g_ylo + (size_t)(b * TDIM + t) * CDIM + h * HDIM;
    #pragma unroll
    for (int i = 0; i < 64; i += 2) {
        float v0 = __uint_as_float(r[i])   * inv;
        float v1 = __uint_as_float(r[i+1]) * inv;
        __nv_bfloat162 h2 = __floats2bfloat162_rn(v0, v1);
        float l0 = v0 - __bfloat162float(__low2bfloat16(h2));
        float l1 = v1 - __bfloat162float(__high2bfloat16(h2));
        *(__nv_bfloat162*)(yh + i) = h2;
        *(__nv_bfloat162*)(yl + i) = __floats2bfloat162_rn(l0, l1);
    }
    __syncthreads();
    if (wid == 0) { TC_DEALLOC(tmem, 64); }
#else
    // -------- FFMA fallback (compile-only on non-103a pass) ------------------
    float acc[64];
    #pragma unroll
    for (int i = 0; i < 64; i++) acc[i] = 0.f;
    for (int s = 0; s <= t; s++) {
        float p = __fdividef(1.0f, 1.0f + __expf(-(sq + skb[s])));
        const float* vr = vsrc + (size_t)s * QKV_COLS;
        #pragma unroll
        for (int i = 0; i < 64; i++) acc[i] = fmaf(p, vr[i], acc[i]);
    }
    const float inv = 1.0f / (45.25483399593904f + 1e-6f);
    __nv_bfloat16* yh = g_yhi + (size_t)(b * TDIM + t) * CDIM + h * HDIM;
    __nv_bfloat16* yl = g_ylo + (size_t)(b * TDIM + t) * CDIM + h * HDIM;
    #pragma unroll
    for (int i = 0; i < 64; i += 2) {
        float v0 = acc[i] * inv, v1 = acc[i+1] * inv;
        __nv_bfloat162 h2 = __floats2bfloat162_rn(v0, v1);
        float l0 = v0 - __bfloat162float(__low2bfloat16(h2));
        float l1 = v1 - __bfloat162float(__high2bfloat16(h2));
        *(__nv_bfloat162*)(yh + i) = h2;
        *(__nv_bfloat162*)(yl + i) = __floats2bfloat162_rn(l0, l1);
    }
#endif
}

// -----------------------------------------------------------------------------
extern "C" void kernel_launch(void* const* d_in, const int* in_sizes, int n_in,
                              void* d_out, int out_size)
{
    const float* x     = (const float*)d_in[0];
    const float* cosb  = (const float*)d_in[1];
    const float* sinb  = (const float*)d_in[2];
    const float* Wq    = (const float*)d_in[3];
    const float* Wk    = (const float*)d_in[4];
    const float* Wv    = (const float*)d_in[5];
    const float* Wproj = (const float*)d_in[6];
    const float* wb    = (const float*)d_in[7];
    float* out = (float*)d_out;

    float *qkv, *sq, *sk;
    cudaGetSymbolAddress((void**)&qkv, g_qkv);
    cudaGetSymbolAddress((void**)&sq,  g_sq);
    cudaGetSymbolAddress((void**)&sk,  g_sk);

    __nv_bfloat16 *xhi, *xlo, *wqkvh, *wqkvl, *wph, *wpl, *yhi, *ylo;
    cudaGetSymbolAddress((void**)&xhi,   g_xhi);    cudaGetSymbolAddress((void**)&xlo,   g_xlo);
    cudaGetSymbolAddress((void**)&wqkvh, g_wqkvh);  cudaGetSymbolAddress((void**)&wqkvl, g_wqkvl);
    cudaGetSymbolAddress((void**)&wph,   g_wph);    cudaGetSymbolAddress((void**)&wpl,   g_wpl);
    cudaGetSymbolAddress((void**)&yhi,   g_yhi);    cudaGetSymbolAddress((void**)&ylo,   g_ylo);

    cudaFuncSetAttribute(gemm3_bf16,    cudaFuncAttributeMaxDynamicSharedMemorySize, SMEM_GEMM);
    cudaFuncSetAttribute(braid_attn_tc, cudaFuncAttributeMaxDynamicSharedMemorySize, SMEM_ATTN);

    // hi/lo bf16 splits (Wq|Wk|Wv go into one fused weight buffer)
    {
        int n4;
        n4 = MROWS*CDIM/4;      split_bf16<<<(n4+255)/256, 256>>>(x,     xhi, xlo, n4);
        n4 = CDIM*CDIM/4;       split_bf16<<<(n4+255)/256, 256>>>(Wq,    wqkvh,                wqkvl,                n4);
        n4 = (NKV*HDIM)*CDIM/4; split_bf16<<<(n4+255)/256, 256>>>(Wk,    wqkvh + 1024*CDIM,    wqkvl + 1024*CDIM,    n4);
        n4 = (NKV*HDIM)*CDIM/4; split_bf16<<<(n4+255)/256, 256>>>(Wv,    wqkvh + 1536*CDIM,    wqkvl + 1536*CDIM,    n4);
        n4 = CDIM*CDIM/4;       split_bf16<<<(n4+255)/256, 256>>>(Wproj, wph, wpl, n4);
    }

    // fused QKV projection: [4096 x 2048] = x @ [Wq|Wk|Wv]^T on tcgen05
    gemm3_bf16<<<dim3(QKV_COLS/128, MROWS/128), 256, SMEM_GEMM>>>(
        xhi, xlo, wqkvh, wqkvl, qkv, MROWS, QKV_COLS, CDIM);

    // RoPE + RMSnorm + braid scalar (q cols 0..1023, k cols 1024..1535)
    rope_braid<<<(BDIM*TDIM*NH  + 7) / 8, 256>>>(qkv, sq, cosb, sinb, wb, NH,  0);
    rope_braid<<<(BDIM*TDIM*NKV + 7) / 8, 256>>>(qkv, sk, cosb, sinb, wb, NKV, 1024);

    // tensor-core sigmoid-braid causal attention -> y (bf16 hi/lo)
    braid_attn_tc<<<dim3(TDIM/128, BDIM*NH), 128, SMEM_ATTN>>>();

    // output projection
    gemm3_bf16<<<dim3(CDIM/128, MROWS/128), 256, SMEM_GEMM>>>(
        yhi, ylo, wph, wpl, out, MROWS, CDIM, CDIM);
}